// round 14
// baseline (speedup 1.0000x reference)
#include <cuda_runtime.h>
#include <cuda_fp16.h>
#include <cstdint>

#define NT 384
#define NTP 256
#define ROWS 192
#define NCHUNK 8
// smem byte offsets (R11 layout)
#define SM_A    0         // 192 rows x 264 fp16 (stride 528B) = 101376
#define SM_W1   101376    // 64n x 264k = 33792
#define SM_W2   135168    // 128n x 72k (stride 144B) = 18432
#define SM_H    153600    // 192 x 72 fp16 (stride 144B) = 27648
#define SM_TOTAL 181248

__device__ float g_agg[50000 * 128];
// weight images: fp16 hi only, chunk-contiguous
__device__ __align__(16) __half g_w1m[8 * 64 * 264];
__device__ __align__(16) __half g_w2m[8 * 128 * 72];
__device__ __align__(16) __half g_w1u[8 * 64 * 264];
__device__ __align__(16) __half g_w2u[8 * 128 * 72];

__device__ __forceinline__ uint32_t smem_u32(const void* p) {
    uint32_t a;
    asm("{ .reg .u64 t; cvta.to.shared.u64 t, %1; cvt.u32.u64 %0, t; }" : "=r"(a) : "l"(p));
    return a;
}
__device__ __forceinline__ void ldm4(uint32_t addr, uint32_t* r) {
    asm volatile("ldmatrix.sync.aligned.m8n8.x4.shared.b16 {%0,%1,%2,%3}, [%4];"
                 : "=r"(r[0]), "=r"(r[1]), "=r"(r[2]), "=r"(r[3]) : "r"(addr));
}
__device__ __forceinline__ void mma_f16(float* c, const uint32_t* a,
                                        uint32_t b0, uint32_t b1) {
    asm volatile(
        "mma.sync.aligned.m16n8k16.row.col.f32.f16.f16.f32 "
        "{%0,%1,%2,%3}, {%4,%5,%6,%7}, {%8,%9}, {%0,%1,%2,%3};"
        : "+f"(c[0]), "+f"(c[1]), "+f"(c[2]), "+f"(c[3])
        : "r"(a[0]), "r"(a[1]), "r"(a[2]), "r"(a[3]), "r"(b0), "r"(b1));
}
__device__ __forceinline__ void cp16(uint32_t dst, const void* src) {
    asm volatile("cp.async.cg.shared.global [%0], [%1], 16;" :: "r"(dst), "l"(src));
}
__device__ __forceinline__ uint32_t h2bits(__half2 v) {
    return *reinterpret_cast<uint32_t*>(&v);
}
__device__ __forceinline__ void red_v2(float* p, float a, float b) {
    asm volatile("red.global.add.v2.f32 [%0], {%1,%2};"
                 :: "l"(p), "f"(a), "f"(b) : "memory");
}

// ---- merged prep (256 threads): zero agg + 4 hi-only weight images ----
// blocks: zero [0,6250) | w1m [6250,6762) | w2m [6762,7018) | w1u [7018,7530) | w2u [7530,7786)
__global__ void prep_all(const float* __restrict__ W1m, const float* __restrict__ W2m,
                         const float* __restrict__ W1u, const float* __restrict__ W2u,
                         float* __restrict__ agg) {
    int b = blockIdx.x, tid = threadIdx.x;
    if (b < 6250) {
        ((float4*)agg)[b * NTP + tid] = make_float4(0.f, 0.f, 0.f, 0.f);
    } else if (b < 6762 || (b >= 7018 && b < 7530)) {   // W1 [256k x 512n] -> [8 c(n64)][64n][264k]
        bool msg = (b < 6762);
        const float* W = msg ? W1m : W1u;
        __half* hi = msg ? g_w1m : g_w1u;
        int idx = (b - (msg ? 6250 : 7018)) * NTP + tid;
        int k = idx >> 9, n = idx & 511;
        hi[(n >> 6) * 16896 + (n & 63) * 264 + k] = __float2half_rn(W[idx]);
    } else {                                            // W2 [512k x 128n] -> [8 c(k64)][128n][72k]
        bool msg = (b < 7018);
        const float* W = msg ? W2m : W2u;
        __half* hi = msg ? g_w2m : g_w2u;
        int idx = (b - (msg ? 6762 : 7530)) * NTP + tid;
        int k = idx >> 7, n = idx & 127;
        hi[(k >> 6) * 9216 + n * 72 + (k & 63)] = __float2half_rn(W[idx]);
    }
}

__device__ __forceinline__ void prefetch_w1(uint32_t sb, int c,
                                            const __half* w1, int tid) {
    const char* s = ((const char*)w1) + c * 33792;
#pragma unroll
    for (int j = 0; j < 6; ++j) {
        int idx = tid + j * NT;
        if (idx < 2112) cp16(sb + SM_W1 + idx * 16, s + idx * 16);
    }
    asm volatile("cp.async.commit_group;");
}
__device__ __forceinline__ void prefetch_w2(uint32_t sb, int c,
                                            const __half* w2, int tid) {
    const char* s = ((const char*)w2) + c * 18432;
#pragma unroll
    for (int j = 0; j < 3; ++j) {
        int idx = tid + j * NT;
        if (idx < 1152) cp16(sb + SM_W2 + idx * 16, s + idx * 16);
    }
    asm volatile("cp.async.commit_group;");
}

// Fused 2-layer MLP, 192 rows/CTA, 384 threads (12 warps: 6m x 2n, warp m32),
// single-term fp16 mma.sync, R11 split-prefetch pipeline.
template <bool IS_EDGE>
__global__ __launch_bounds__(NT, 1)
void mlp_mma(const float* __restrict__ x, const float* __restrict__ second,
             const int* __restrict__ eidx,
             const __half* __restrict__ w1, const __half* __restrict__ w2,
             const float* __restrict__ b1, const float* __restrict__ b2,
             float* __restrict__ out, int M, int E) {
    extern __shared__ __align__(16) unsigned char smem[];
    const uint32_t sb = smem_u32(smem);
    const int tid = threadIdx.x;
    const int lane = tid & 31;
    const int wid = tid >> 5;
    const int wm = wid % 6, wn = wid / 6;   // 6 m-warps(32 rows) x 2 n-warps
    const int rowbase = blockIdx.x * ROWS;

    prefetch_w1(sb, 0, w1, tid);
    prefetch_w2(sb, 0, w2, tid);

    // ---- gather A = [feat_i(128) | feat_j(128)] -> fp16 smem (1 half-row/thread) ----
    {
        int r = tid >> 1, half = tid & 1;
        int row = rowbase + r;
        const float* src;
        if (IS_EDGE) {
            int e = (row < E) ? row : 0;
            int node = half ? eidx[e] : eidx[E + e];   // half0 = i, half1 = j
            src = x + (size_t)node * 128;
        } else {
            int rr = (row < M) ? row : 0;
            src = (half ? second : x) + (size_t)rr * 128;
        }
        uint32_t abase = sb + SM_A + (uint32_t)(r * 528 + half * 256);
#pragma unroll
        for (int jj = 0; jj < 32; ++jj) {
            float4 v = *(const float4*)(src + jj * 4);
            uint32_t h0 = h2bits(__float22half2_rn(make_float2(v.x, v.y)));
            uint32_t h1 = h2bits(__float22half2_rn(make_float2(v.z, v.w)));
            asm volatile("st.shared.v2.b32 [%0], {%1,%2};"
                         :: "r"(abase + jj * 8), "r"(h0), "r"(h1) : "memory");
        }
    }

    // ldmatrix base addresses (2 m-frags per warp)
    uint32_t aB[2], hB[2];
#pragma unroll
    for (int mf = 0; mf < 2; ++mf) {
        aB[mf] = sb + SM_A +
            (uint32_t)((wm * 32 + mf * 16 + (lane & 15)) * 528 + ((lane >> 4) & 1) * 16);
        hB[mf] = sb + SM_H +
            (uint32_t)((wm * 32 + mf * 16 + (lane & 15)) * 144 + ((lane >> 4) & 1) * 16);
    }
    const uint32_t bB0 = sb + SM_W1 +
        (uint32_t)((wn * 32 + (lane & 7) + ((lane >> 4) & 1) * 8) * 528 +
                   ((lane >> 3) & 1) * 16);
    const uint32_t bB1 = bB0 + 16 * 528;
    uint32_t w2B[4];
#pragma unroll
    for (int p = 0; p < 4; ++p)
        w2B[p] = sb + SM_W2 +
            (uint32_t)((wn * 64 + p * 16 + (lane & 7) + ((lane >> 4) & 1) * 8) * 144 +
                       ((lane >> 3) & 1) * 16);

    float acc2[64];
#pragma unroll
    for (int i = 0; i < 64; ++i) acc2[i] = 0.f;

    const int rsub = lane >> 2;        // 0..7
    const int cc = (lane & 3) * 2;

    for (int c = 0; c < NCHUNK; ++c) {
        asm volatile("cp.async.wait_group 1;");   // W1(c) ready
        __syncthreads();

        // ---- GEMM1: acc1[32rows x 32cols per warp], K=256, single term ----
        float acc1[32];
#pragma unroll
        for (int i = 0; i < 32; ++i) acc1[i] = 0.f;
#pragma unroll
        for (int s = 0; s < 16; ++s) {
            uint32_t a0[4], a1[4], b0[4], b1r[4];
            ldm4(aB[0] + s * 32, a0);
            ldm4(aB[1] + s * 32, a1);
            ldm4(bB0 + s * 32, b0);
            ldm4(bB1 + s * 32, b1r);
            mma_f16(acc1 + 0,  a0, b0[0], b0[1]);
            mma_f16(acc1 + 4,  a0, b0[2], b0[3]);
            mma_f16(acc1 + 8,  a0, b1r[0], b1r[1]);
            mma_f16(acc1 + 12, a0, b1r[2], b1r[3]);
            mma_f16(acc1 + 16, a1, b0[0], b0[1]);
            mma_f16(acc1 + 20, a1, b0[2], b0[3]);
            mma_f16(acc1 + 24, a1, b1r[0], b1r[1]);
            mma_f16(acc1 + 28, a1, b1r[2], b1r[3]);
        }

        // ---- epilogue: relu(acc1 + b1) -> fp16 H smem ----
#pragma unroll
        for (int mf = 0; mf < 2; ++mf) {
#pragma unroll
            for (int nq = 0; nq < 4; ++nq) {
                const float* ac = acc1 + mf * 16 + nq * 4;
                int gcol = c * 64 + wn * 32 + nq * 8 + cc;
                float ba = __ldg(b1 + gcol), bb = __ldg(b1 + gcol + 1);
                float v00 = fmaxf(ac[0] + ba, 0.f);
                float v01 = fmaxf(ac[1] + bb, 0.f);
                float v10 = fmaxf(ac[2] + ba, 0.f);
                float v11 = fmaxf(ac[3] + bb, 0.f);
                uint32_t p0 = h2bits(__float22half2_rn(make_float2(v00, v01)));
                uint32_t p1 = h2bits(__float22half2_rn(make_float2(v10, v11)));
                int hcol = wn * 32 + nq * 8 + cc;
                int r0 = wm * 32 + mf * 16 + rsub;
                uint32_t a0 = sb + SM_H + (uint32_t)(r0 * 144 + hcol * 2);
                asm volatile("st.shared.b32 [%0], %1;" :: "r"(a0), "r"(p0) : "memory");
                asm volatile("st.shared.b32 [%0], %1;" :: "r"(a0 + 8 * 144), "r"(p1) : "memory");
            }
        }
        __syncthreads();   // H visible; W1 slab free

        if (c + 1 < NCHUNK) {
            prefetch_w1(sb, c + 1, w1, tid);
            asm volatile("cp.async.wait_group 1;");   // W2(c) ready
        } else {
            asm volatile("cp.async.wait_group 0;");
        }
        __syncthreads();

        // ---- GEMM2: acc2 += H[192x64] @ W2[64x128], single term ----
#pragma unroll
        for (int s = 0; s < 4; ++s) {
            uint32_t h0[4], h1[4];
            ldm4(hB[0] + s * 32, h0);
            ldm4(hB[1] + s * 32, h1);
#pragma unroll
            for (int p = 0; p < 4; ++p) {
                uint32_t bw[4];
                ldm4(w2B[p] + s * 32, bw);
                mma_f16(acc2 + p * 8 + 0,      h0, bw[0], bw[1]);
                mma_f16(acc2 + p * 8 + 4,      h0, bw[2], bw[3]);
                mma_f16(acc2 + 32 + p * 8 + 0, h1, bw[0], bw[1]);
                mma_f16(acc2 + 32 + p * 8 + 4, h1, bw[2], bw[3]);
            }
        }
        __syncthreads();   // W2 slab free
        if (c + 1 < NCHUNK) prefetch_w2(sb, c + 1, w2, tid);
    }

    // ---- final epilogue: out = acc2 + b2 (v2 reductions / stores) ----
#pragma unroll
    for (int mf = 0; mf < 2; ++mf) {
        int e0 = rowbase + wm * 32 + mf * 16 + rsub;
        int e1 = e0 + 8;
        int tgt0 = 0, tgt1 = 0;
        if (IS_EDGE) {
            tgt0 = (e0 < E) ? eidx[E + e0] : 0;
            tgt1 = (e1 < E) ? eidx[E + e1] : 0;
        }
#pragma unroll
        for (int p = 0; p < 4; ++p) {
#pragma unroll
            for (int t = 0; t < 2; ++t) {
                const float* ac = acc2 + mf * 32 + p * 8 + t * 4;
                int col = wn * 64 + p * 16 + t * 8 + cc;
                float ba = __ldg(b2 + col), bb = __ldg(b2 + col + 1);
                float v00 = ac[0] + ba, v01 = ac[1] + bb;
                float v10 = ac[2] + ba, v11 = ac[3] + bb;
                if (IS_EDGE) {
                    if (e0 < E) red_v2(out + (size_t)tgt0 * 128 + col, v00, v01);
                    if (e1 < E) red_v2(out + (size_t)tgt1 * 128 + col, v10, v11);
                } else {
                    if (e0 < M) *(float2*)(out + (size_t)e0 * 128 + col) = make_float2(v00, v01);
                    if (e1 < M) *(float2*)(out + (size_t)e1 * 128 + col) = make_float2(v10, v11);
                }
            }
        }
    }
}

extern "C" void kernel_launch(void* const* d_in, const int* in_sizes, int n_in,
                              void* d_out, int out_size) {
    const float* x   = (const float*)d_in[0];
    const int* eidx  = (const int*)d_in[2];   // JAX demotes int64 -> int32
    const float* W1m = (const float*)d_in[3];
    const float* b1m = (const float*)d_in[4];
    const float* W2m = (const float*)d_in[5];
    const float* b2m = (const float*)d_in[6];
    const float* W1u = (const float*)d_in[7];
    const float* b1u = (const float*)d_in[8];
    const float* W2u = (const float*)d_in[9];
    const float* b2u = (const float*)d_in[10];
    float* out = (float*)d_out;

    int N = in_sizes[0] / 128;
    int E = in_sizes[2] / 2;

    float* agg; cudaGetSymbolAddress((void**)&agg, g_agg);
    __half *w1m, *w2m, *w1u, *w2u;
    cudaGetSymbolAddress((void**)&w1m, g_w1m);
    cudaGetSymbolAddress((void**)&w2m, g_w2m);
    cudaGetSymbolAddress((void**)&w1u, g_w1u);
    cudaGetSymbolAddress((void**)&w2u, g_w2u);

    cudaFuncSetAttribute((const void*)mlp_mma<true>,
                         cudaFuncAttributeMaxDynamicSharedMemorySize, SM_TOTAL);
    cudaFuncSetAttribute((const void*)mlp_mma<false>,
                         cudaFuncAttributeMaxDynamicSharedMemorySize, SM_TOTAL);

    prep_all<<<7786, NTP>>>(W1m, W2m, W1u, W2u, agg);

    mlp_mma<true><<<(E + ROWS - 1) / ROWS, NT, SM_TOTAL>>>(
        x, x, eidx, w1m, w2m, b1m, b2m, agg, E, E);

    mlp_mma<false><<<(N + ROWS - 1) / ROWS, NT, SM_TOTAL>>>(
        x, agg, nullptr, w1u, w2u, b1u, b2u, out, N, 0);
}

// round 15
// speedup vs baseline: 1.7379x; 1.7379x over previous
#include <cuda_runtime.h>
#include <cuda_fp16.h>
#include <cstdint>

#define NTP 256

__device__ float g_agg[50000 * 128];
__device__ __align__(16) __half g_P[50000 * 512];   // x@W1m_top + b1m  (fp16)
__device__ __align__(16) __half g_Q[50000 * 512];   // x@W1m_bot        (fp16)
// weight images
__device__ __align__(16) __half g_w1pre[16 * 64 * 136]; // [16 nchunk64][64n][136k(128 used)]
__device__ __align__(16) __half g_w2m[8 * 128 * 72];    // [8 kchunk64][128n][72k]
__device__ __align__(16) __half g_w1u[8 * 64 * 264];    // [8 nchunk64][64n][264k(256 used)]
__device__ __align__(16) __half g_w2u[8 * 128 * 72];

__device__ __forceinline__ uint32_t smem_u32(const void* p) {
    uint32_t a;
    asm("{ .reg .u64 t; cvta.to.shared.u64 t, %1; cvt.u32.u64 %0, t; }" : "=r"(a) : "l"(p));
    return a;
}
__device__ __forceinline__ void ldm4(uint32_t addr, uint32_t* r) {
    asm volatile("ldmatrix.sync.aligned.m8n8.x4.shared.b16 {%0,%1,%2,%3}, [%4];"
                 : "=r"(r[0]), "=r"(r[1]), "=r"(r[2]), "=r"(r[3]) : "r"(addr));
}
__device__ __forceinline__ void mma_f16(float* c, const uint32_t* a,
                                        uint32_t b0, uint32_t b1) {
    asm volatile(
        "mma.sync.aligned.m16n8k16.row.col.f32.f16.f16.f32 "
        "{%0,%1,%2,%3}, {%4,%5,%6,%7}, {%8,%9}, {%0,%1,%2,%3};"
        : "+f"(c[0]), "+f"(c[1]), "+f"(c[2]), "+f"(c[3])
        : "r"(a[0]), "r"(a[1]), "r"(a[2]), "r"(a[3]), "r"(b0), "r"(b1));
}
__device__ __forceinline__ void cp16(uint32_t dst, const void* src) {
    asm volatile("cp.async.cg.shared.global [%0], [%1], 16;" :: "r"(dst), "l"(src));
}
__device__ __forceinline__ uint32_t h2bits(__half2 v) {
    return *reinterpret_cast<uint32_t*>(&v);
}
__device__ __forceinline__ void red_v2(float* p, float a, float b) {
    asm volatile("red.global.add.v2.f32 [%0], {%1,%2};"
                 :: "l"(p), "f"(a), "f"(b) : "memory");
}

// ---- merged prep: zero agg + weight images ----
// blocks: agg [0,6250) | w1pre [6250,6762) | w2m [6762,7018) | w1u [7018,7530) | w2u [7530,7786)
__global__ void prep_all(const float* __restrict__ W1m, const float* __restrict__ W2m,
                         const float* __restrict__ W1u, const float* __restrict__ W2u,
                         float* __restrict__ agg) {
    int b = blockIdx.x, tid = threadIdx.x;
    if (b < 6250) {
        ((float4*)agg)[b * NTP + tid] = make_float4(0.f, 0.f, 0.f, 0.f);
    } else if (b < 6762) {          // w1pre: W1m[256k x 512n] -> ncat = n + 512*(k>=128)
        int idx = (b - 6250) * NTP + tid;
        int k = idx >> 9, n = idx & 511;
        int ncat = (k < 128) ? n : n + 512;
        int kk = k & 127;
        g_w1pre[(ncat >> 6) * 8704 + (ncat & 63) * 136 + kk] = __float2half_rn(W1m[idx]);
    } else if (b < 7018) {          // w2m: [8 c(k64)][128n][72k]
        int idx = (b - 6762) * NTP + tid;
        int k = idx >> 7, n = idx & 127;
        g_w2m[(k >> 6) * 9216 + n * 72 + (k & 63)] = __float2half_rn(W2m[idx]);
    } else if (b < 7530) {          // w1u: [8 c(n64)][64n][264k]
        int idx = (b - 7018) * NTP + tid;
        int k = idx >> 9, n = idx & 511;
        g_w1u[(n >> 6) * 16896 + (n & 63) * 264 + k] = __float2half_rn(W1u[idx]);
    } else {                        // w2u
        int idx = (b - 7530) * NTP + tid;
        int k = idx >> 7, n = idx & 127;
        g_w2u[(k >> 6) * 9216 + n * 72 + (k & 63)] = __float2half_rn(W2u[idx]);
    }
}

// ---- precompute P = x@W1top + b1, Q = x@W1bot (fp16 out) ----
// 128 rows/CTA, 256 thr (4m x 2n warps), 16 n-chunks of 64 (first 8 -> P, rest -> Q)
#define PQ_SMA 0          // 128 x 136 halfs (stride 272B) = 34816
#define PQ_SMW 34816      // 2 bufs x 17408
#define PQ_TOTAL 69632
__global__ __launch_bounds__(256, 1)
void pq_kernel(const float* __restrict__ x, const float* __restrict__ b1,
               __half* __restrict__ P, __half* __restrict__ Q, int N) {
    extern __shared__ __align__(16) unsigned char smem[];
    const uint32_t sb = smem_u32(smem);
    const int tid = threadIdx.x;
    const int lane = tid & 31;
    const int wid = tid >> 5;
    const int wm = wid & 3, wn = wid >> 2;
    const int rowb = blockIdx.x * 128;

    // prefetch chunk 0,1 weights
#pragma unroll
    for (int cb = 0; cb < 2; ++cb) {
        const char* s = ((const char*)g_w1pre) + cb * 17408;
#pragma unroll
        for (int j = 0; j < 5; ++j) {
            int idx = tid + j * 256;
            if (idx < 1088) cp16(sb + PQ_SMW + cb * 17408 + idx * 16, s + idx * 16);
        }
        asm volatile("cp.async.commit_group;");
    }

    // load x rows -> fp16 smem
    {
        int r = tid >> 1, half = tid & 1;
        int g = rowb + r;
        const float* src = x + (size_t)((g < N) ? g : 0) * 128 + half * 64;
        uint32_t abase = sb + PQ_SMA + (uint32_t)(r * 272 + half * 128);
#pragma unroll
        for (int jj = 0; jj < 16; ++jj) {
            float4 v = *(const float4*)(src + jj * 4);
            uint32_t h0 = h2bits(__float22half2_rn(make_float2(v.x, v.y)));
            uint32_t h1 = h2bits(__float22half2_rn(make_float2(v.z, v.w)));
            asm volatile("st.shared.v2.b32 [%0], {%1,%2};"
                         :: "r"(abase + jj * 8), "r"(h0), "r"(h1) : "memory");
        }
    }

    uint32_t aB[2];
#pragma unroll
    for (int mf = 0; mf < 2; ++mf)
        aB[mf] = sb + PQ_SMA +
            (uint32_t)((wm * 32 + mf * 16 + (lane & 15)) * 272 + ((lane >> 4) & 1) * 16);
    const uint32_t bOff = (uint32_t)((wn * 32 + (lane & 7) + ((lane >> 4) & 1) * 8) * 272 +
                                     ((lane >> 3) & 1) * 16);
    const int rsub = lane >> 2;
    const int cc = (lane & 3) * 2;

    for (int c = 0; c < 16; ++c) {
        if (c == 15) asm volatile("cp.async.wait_group 0;");
        else         asm volatile("cp.async.wait_group 1;");
        __syncthreads();
        const uint32_t wb = sb + PQ_SMW + (uint32_t)(c & 1) * 17408;

        float acc[32];
#pragma unroll
        for (int i = 0; i < 32; ++i) acc[i] = 0.f;
#pragma unroll
        for (int s = 0; s < 8; ++s) {
            uint32_t a0[4], a1[4], b0[4], b1r[4];
            ldm4(aB[0] + s * 32, a0);
            ldm4(aB[1] + s * 32, a1);
            ldm4(wb + bOff + s * 32, b0);
            ldm4(wb + bOff + 16 * 272 + s * 32, b1r);
            mma_f16(acc + 0,  a0, b0[0], b0[1]);
            mma_f16(acc + 4,  a0, b0[2], b0[3]);
            mma_f16(acc + 8,  a0, b1r[0], b1r[1]);
            mma_f16(acc + 12, a0, b1r[2], b1r[3]);
            mma_f16(acc + 16, a1, b0[0], b0[1]);
            mma_f16(acc + 20, a1, b0[2], b0[3]);
            mma_f16(acc + 24, a1, b1r[0], b1r[1]);
            mma_f16(acc + 28, a1, b1r[2], b1r[3]);
        }
        __syncthreads();
        if (c + 2 < 16) {
            const char* s = ((const char*)g_w1pre) + (c + 2) * 17408;
            uint32_t d = sb + PQ_SMW + (uint32_t)(c & 1) * 17408;
#pragma unroll
            for (int j = 0; j < 5; ++j) {
                int idx = tid + j * 256;
                if (idx < 1088) cp16(d + idx * 16, s + idx * 16);
            }
        }
        asm volatile("cp.async.commit_group;");

        // epilogue -> P/Q fp16
        bool isP = (c < 8);
        __half* dst = isP ? P : Q;
        int colbase = (isP ? c : c - 8) * 64;
#pragma unroll
        for (int mf = 0; mf < 2; ++mf) {
            int r0 = rowb + wm * 32 + mf * 16 + rsub;
#pragma unroll
            for (int ng = 0; ng < 4; ++ng) {
                const float* ac = acc + mf * 16 + ng * 4;
                int col = wn * 32 + ng * 8 + cc;
                float ba = 0.f, bb = 0.f;
                if (isP) { ba = __ldg(b1 + colbase + col); bb = __ldg(b1 + colbase + col + 1); }
                uint32_t v0 = h2bits(__float22half2_rn(make_float2(ac[0] + ba, ac[1] + bb)));
                uint32_t v1 = h2bits(__float22half2_rn(make_float2(ac[2] + ba, ac[3] + bb)));
                if (r0 < N)
                    *(uint32_t*)(dst + (size_t)r0 * 512 + colbase + col) = v0;
                if (r0 + 8 < N)
                    *(uint32_t*)(dst + (size_t)(r0 + 8) * 512 + colbase + col) = v1;
            }
        }
    }
}

// ---- edge kernel: H = relu(P[i] + Q[j]) ; out[tgt] += H @ W2m + b2 ----
#define E_SMH   0          // 128 x 72 halfs (stride 144B) = 18432
#define E_SMW2  18432      // 3 bufs x 18432
#define E_SMI   73728      // 128 int i + 128 int j
#define E_TOTAL 74752
__global__ __launch_bounds__(256, 2)
void edge_mma(const int* __restrict__ eidx,
              const __half* __restrict__ P, const __half* __restrict__ Q,
              const float* __restrict__ b2, float* __restrict__ out, int E) {
    extern __shared__ __align__(16) unsigned char smem[];
    const uint32_t sb = smem_u32(smem);
    int* sI = (int*)(smem + E_SMI);
    int* sJ = sI + 128;
    const int tid = threadIdx.x;
    const int lane = tid & 31;
    const int wid = tid >> 5;
    const int wm = wid & 3, wn = wid >> 2;
    const int rowbase = blockIdx.x * 128;

    // W2 chunks 0,1 in flight
#pragma unroll
    for (int cb = 0; cb < 2; ++cb) {
        const char* s = ((const char*)g_w2m) + cb * 18432;
#pragma unroll
        for (int j = 0; j < 5; ++j) {
            int idx = tid + j * 256;
            if (idx < 1152) cp16(sb + E_SMW2 + cb * 18432 + idx * 16, s + idx * 16);
        }
        asm volatile("cp.async.commit_group;");
    }

    if (tid < 128) {
        int row = rowbase + tid;
        int e = (row < E) ? row : 0;
        sI[tid] = eidx[E + e];   // target i
        sJ[tid] = eidx[e];       // source j
    }
    __syncthreads();

    const uint32_t hB0 = sb + E_SMH +
        (uint32_t)((wm * 32 + (lane & 15)) * 144 + ((lane >> 4) & 1) * 16);
    const uint32_t hB1 = hB0 + 16 * 144;
    uint32_t w2Off[4];
#pragma unroll
    for (int p = 0; p < 4; ++p)
        w2Off[p] = (uint32_t)((wn * 64 + p * 16 + (lane & 7) + ((lane >> 4) & 1) * 8) * 144 +
                              ((lane >> 3) & 1) * 16);

    float acc2[64];
#pragma unroll
    for (int i = 0; i < 64; ++i) acc2[i] = 0.f;

    const int gr = tid >> 1;         // gather row 0..127
    const int gh = tid & 1;          // col half (32 cols)
    const size_t pRow = (size_t)sI[gr] * 512;
    const size_t qRow = (size_t)sJ[gr] * 512;
    const uint32_t hSt = sb + E_SMH + (uint32_t)(gr * 144 + gh * 64);

    const int rsub = lane >> 2;
    const int cc = (lane & 3) * 2;

    for (int c = 0; c < 8; ++c) {
        if (c == 7) asm volatile("cp.async.wait_group 0;");
        else        asm volatile("cp.async.wait_group 1;");

        // issue gathers for chunk c (land across the barrier)
        const uint4* pp = (const uint4*)(P + pRow + c * 64 + gh * 32);
        const uint4* qq = (const uint4*)(Q + qRow + c * 64 + gh * 32);
        uint4 pv[4], qv[4];
#pragma unroll
        for (int j = 0; j < 4; ++j) { pv[j] = __ldg(pp + j); qv[j] = __ldg(qq + j); }

        __syncthreads();   // GEMM2(c-1) done: H writable, W2 buf (c+2)%3 free

        if (c + 2 < 8) {
            const char* s = ((const char*)g_w2m) + (c + 2) * 18432;
            uint32_t d = sb + E_SMW2 + (uint32_t)((c + 2) % 3) * 18432;
#pragma unroll
            for (int j = 0; j < 5; ++j) {
                int idx = tid + j * 256;
                if (idx < 1152) cp16(d + idx * 16, s + idx * 16);
            }
        }
        asm volatile("cp.async.commit_group;");

        // H = relu(P+Q) -> smem
        const __half2 z2 = __float2half2_rn(0.f);
#pragma unroll
        for (int j = 0; j < 4; ++j) {
            __half2* ph = (__half2*)&pv[j];
            __half2* qh = (__half2*)&qv[j];
            uint32_t o[4];
#pragma unroll
            for (int q = 0; q < 4; ++q)
                o[q] = h2bits(__hmax2(__hadd2(ph[q], qh[q]), z2));
            asm volatile("st.shared.v4.b32 [%0], {%1,%2,%3,%4};"
                         :: "r"(hSt + j * 16), "r"(o[0]), "r"(o[1]), "r"(o[2]), "r"(o[3])
                         : "memory");
        }
        __syncthreads();   // H visible

        // GEMM2: acc2 += H[128x64] @ W2chunk[64x128]
        const uint32_t w2b = sb + E_SMW2 + (uint32_t)(c % 3) * 18432;
#pragma unroll
        for (int s = 0; s < 4; ++s) {
            uint32_t h0[4], h1[4];
            ldm4(hB0 + s * 32, h0);
            ldm4(hB1 + s * 32, h1);
#pragma unroll
            for (int p = 0; p < 4; ++p) {
                uint32_t bw[4];
                ldm4(w2b + w2Off[p] + s * 32, bw);
                mma_f16(acc2 + p * 8 + 0,      h0, bw[0], bw[1]);
                mma_f16(acc2 + p * 8 + 4,      h0, bw[2], bw[3]);
                mma_f16(acc2 + 32 + p * 8 + 0, h1, bw[0], bw[1]);
                mma_f16(acc2 + 32 + p * 8 + 4, h1, bw[2], bw[3]);
            }
        }
    }

    // scatter: out[tgt] += acc2 + b2
#pragma unroll
    for (int mf = 0; mf < 2; ++mf) {
        int e0 = rowbase + wm * 32 + mf * 16 + rsub;
        int e1 = e0 + 8;
        int tgt0 = sI[wm * 32 + mf * 16 + rsub];
        int tgt1 = sI[wm * 32 + mf * 16 + rsub + 8];
#pragma unroll
        for (int p = 0; p < 4; ++p) {
#pragma unroll
            for (int t = 0; t < 2; ++t) {
                const float* ac = acc2 + mf * 32 + p * 8 + t * 4;
                int col = wn * 64 + p * 16 + t * 8 + cc;
                float ba = __ldg(b2 + col), bb = __ldg(b2 + col + 1);
                if (e0 < E) red_v2(out + (size_t)tgt0 * 128 + col, ac[0] + ba, ac[1] + bb);
                if (e1 < E) red_v2(out + (size_t)tgt1 * 128 + col, ac[2] + ba, ac[3] + bb);
            }
        }
    }
}

// ---- node kernel: R11 champion path (u = [x|agg] @ MLPu) ----
#define N_ROWS 192
#define N_SMA    0
#define N_SMW1   101376
#define N_SMW2   135168
#define N_SMH    153600
#define N_TOTAL  181248
__global__ __launch_bounds__(256, 1)
void node_mma(const float* __restrict__ x, const float* __restrict__ agg,
              const float* __restrict__ b1, const float* __restrict__ b2,
              float* __restrict__ out, int M) {
    extern __shared__ __align__(16) unsigned char smem[];
    const uint32_t sb = smem_u32(smem);
    const int tid = threadIdx.x;
    const int lane = tid & 31;
    const int wid = tid >> 5;
    const int wm = wid & 3, wn = wid >> 2;
    const int rowbase = blockIdx.x * N_ROWS;

    // prefetch chunk0 W1 then W2
    {
        const char* s = (const char*)g_w1u;
#pragma unroll
        for (int j = 0; j < 9; ++j) {
            int idx = tid + j * 256;
            if (idx < 2112) cp16(sb + N_SMW1 + idx * 16, s + idx * 16);
        }
        asm volatile("cp.async.commit_group;");
        const char* s2 = (const char*)g_w2u;
#pragma unroll
        for (int j = 0; j < 5; ++j) {
            int idx = tid + j * 256;
            if (idx < 1152) cp16(sb + N_SMW2 + idx * 16, s2 + idx * 16);
        }
        asm volatile("cp.async.commit_group;");
    }

    for (int idx = tid; idx < N_ROWS * 2; idx += 256) {
        int r = idx >> 1, half = idx & 1;
        int row = rowbase + r;
        int rr = (row < M) ? row : 0;
        const float* src = (half ? agg : x) + (size_t)rr * 128;
        uint32_t abase = sb + N_SMA + (uint32_t)(r * 528 + half * 256);
#pragma unroll
        for (int jj = 0; jj < 32; ++jj) {
            float4 v = *(const float4*)(src + jj * 4);
            uint32_t h0 = h2bits(__float22half2_rn(make_float2(v.x, v.y)));
            uint32_t h1 = h2bits(__float22half2_rn(make_float2(v.z, v.w)));
            asm volatile("st.shared.v2.b32 [%0], {%1,%2};"
                         :: "r"(abase + jj * 8), "r"(h0), "r"(h1) : "memory");
        }
    }

    uint32_t aB[3], hB[3];
#pragma unroll
    for (int mf = 0; mf < 3; ++mf) {
        aB[mf] = sb + N_SMA +
            (uint32_t)((wm * 48 + mf * 16 + (lane & 15)) * 528 + ((lane >> 4) & 1) * 16);
        hB[mf] = sb + N_SMH +
            (uint32_t)((wm * 48 + mf * 16 + (lane & 15)) * 144 + ((lane >> 4) & 1) * 16);
    }
    const uint32_t bB0 = sb + N_SMW1 +
        (uint32_t)((wn * 32 + (lane & 7) + ((lane >> 4) & 1) * 8) * 528 +
                   ((lane >> 3) & 1) * 16);
    const uint32_t bB1 = bB0 + 16 * 528;
    uint32_t w2B[4];
#pragma unroll
    for (int p = 0; p < 4; ++p)
        w2B[p] = sb + N_SMW2 +
            (uint32_t)((wn * 64 + p * 16 + (lane & 7) + ((lane >> 4) & 1) * 8) * 144 +
                       ((lane >> 3) & 1) * 16);

    float acc2[96];
#pragma unroll
    for (int i = 0; i < 96; ++i) acc2[i] = 0.f;
    const int rsub = lane >> 2;
    const int cc = (lane & 3) * 2;

    for (int c = 0; c < 8; ++c) {
        asm volatile("cp.async.wait_group 1;");
        __syncthreads();
        float acc1[48];
#pragma unroll
        for (int i = 0; i < 48; ++i) acc1[i] = 0.f;
#pragma unroll
        for (int s = 0; s < 16; ++s) {
            uint32_t a0[4], a1[4], a2[4], b0[4], b1r[4];
            ldm4(aB[0] + s * 32, a0);
            ldm4(aB[1] + s * 32, a1);
            ldm4(aB[2] + s * 32, a2);
            ldm4(bB0 + s * 32, b0);
            ldm4(bB1 + s * 32, b1r);
            mma_f16(acc1 + 0,  a0, b0[0], b0[1]);
            mma_f16(acc1 + 4,  a0, b0[2], b0[3]);
            mma_f16(acc1 + 8,  a0, b1r[0], b1r[1]);
            mma_f16(acc1 + 12, a0, b1r[2], b1r[3]);
            mma_f16(acc1 + 16, a1, b0[0], b0[1]);
            mma_f16(acc1 + 20, a1, b0[2], b0[3]);
            mma_f16(acc1 + 24, a1, b1r[0], b1r[1]);
            mma_f16(acc1 + 28, a1, b1r[2], b1r[3]);
            mma_f16(acc1 + 32, a2, b0[0], b0[1]);
            mma_f16(acc1 + 36, a2, b0[2], b0[3]);
            mma_f16(acc1 + 40, a2, b1r[0], b1r[1]);
            mma_f16(acc1 + 44, a2, b1r[2], b1r[3]);
        }
#pragma unroll
        for (int mf = 0; mf < 3; ++mf) {
#pragma unroll
            for (int nq = 0; nq < 4; ++nq) {
                const float* ac = acc1 + mf * 16 + nq * 4;
                int gcol = c * 64 + wn * 32 + nq * 8 + cc;
                float ba = __ldg(b1 + gcol), bb = __ldg(b1 + gcol + 1);
                float v00 = fmaxf(ac[0] + ba, 0.f);
                float v01 = fmaxf(ac[1] + bb, 0.f);
                float v10 = fmaxf(ac[2] + ba, 0.f);
                float v11 = fmaxf(ac[3] + bb, 0.f);
                uint32_t p0 = h2bits(__float22half2_rn(make_float2(v00, v01)));
                uint32_t p1 = h2bits(__float22half2_rn(make_float2(v10, v11)));
                int hcol = wn * 32 + nq * 8 + cc;
                int r0 = wm * 48 + mf * 16 + rsub;
                uint32_t a0 = sb + N_SMH + (uint32_t)(r0 * 144 + hcol * 2);
                asm volatile("st.shared.b32 [%0], %1;" :: "r"(a0), "r"(p0) : "memory");
                asm volatile("st.shared.b32 [%0], %1;" :: "r"(a0 + 8 * 144), "r"(p1) : "memory");
            }
        }
        __syncthreads();
        if (c + 1 < 8) {
            const char* s = ((const char*)g_w1u) + (c + 1) * 33792;
#pragma unroll
            for (int j = 0; j < 9; ++j) {
                int idx = tid + j * 256;
                if (idx < 2112) cp16(sb + N_SMW1 + idx * 16, s + idx * 16);
            }
            asm volatile("cp.async.commit_group;");
            asm volatile("cp.async.wait_group 1;");
        } else {
            asm volatile("cp.async.wait_group 0;");
        }
        __syncthreads();
#pragma unroll
        for (int s = 0; s < 4; ++s) {
            uint32_t h0[4], h1[4], h2[4];
            ldm4(hB[0] + s * 32, h0);
            ldm4(hB[1] + s * 32, h1);
            ldm4(hB[2] + s * 32, h2);
#pragma unroll
            for (int p = 0; p < 4; ++p) {
                uint32_t bw[4];
                ldm4(w2B[p] + s * 32, bw);
                mma_f16(acc2 + p * 8 + 0,  h0, bw[0], bw[1]);
                mma_f16(acc2 + p * 8 + 4,  h0, bw[2], bw[3]);
                mma_f16(acc2 + 32 + p * 8 + 0, h1, bw[0], bw[1]);
                mma_f16(acc2 + 32 + p * 8 + 4, h1, bw[2], bw[3]);
                mma_f16(acc2 + 64 + p * 8 + 0, h2, bw[0], bw[1]);
                mma_f16(acc2 + 64 + p * 8 + 4, h2, bw[2], bw[3]);
            }
        }
        __syncthreads();
        if (c + 1 < 8) {
            const char* s = ((const char*)g_w2u) + (c + 1) * 18432;
#pragma unroll
            for (int j = 0; j < 5; ++j) {
                int idx = tid + j * 256;
                if (idx < 1152) cp16(sb + N_SMW2 + idx * 16, s + idx * 16);
            }
        }
        asm volatile("cp.async.commit_group;");
    }

#pragma unroll
    for (int mf = 0; mf < 3; ++mf) {
        int e0 = rowbase + wm * 48 + mf * 16 + rsub;
        int e1 = e0 + 8;
#pragma unroll
        for (int p = 0; p < 4; ++p) {
#pragma unroll
            for (int t = 0; t < 2; ++t) {
                const float* ac = acc2 + mf * 32 + p * 8 + t * 4;
                int col = wn * 64 + p * 16 + t * 8 + cc;
                float ba = __ldg(b2 + col), bb = __ldg(b2 + col + 1);
                if (e0 < M) *(float2*)(out + (size_t)e0 * 128 + col) = make_float2(ac[0] + ba, ac[1] + bb);
                if (e1 < M) *(float2*)(out + (size_t)e1 * 128 + col) = make_float2(ac[2] + ba, ac[3] + bb);
            }
        }
    }
}

extern "C" void kernel_launch(void* const* d_in, const int* in_sizes, int n_in,
                              void* d_out, int out_size) {
    const float* x   = (const float*)d_in[0];
    const int* eidx  = (const int*)d_in[2];   // JAX demotes int64 -> int32
    const float* W1m = (const float*)d_in[3];
    const float* b1m = (const float*)d_in[4];
    const float* W2m = (const float*)d_in[5];
    const float* b2m = (const float*)d_in[6];
    const float* W1u = (const float*)d_in[7];
    const float* b1u = (const float*)d_in[8];
    const float* W2u = (const float*)d_in[9];
    const float* b2u = (const float*)d_in[10];
    float* out = (float*)d_out;

    int N = in_sizes[0] / 128;
    int E = in_sizes[2] / 2;

    float* agg; cudaGetSymbolAddress((void**)&agg, g_agg);
    __half *P, *Q;
    cudaGetSymbolAddress((void**)&P, g_P);
    cudaGetSymbolAddress((void**)&Q, g_Q);

    cudaFuncSetAttribute((const void*)pq_kernel,
                         cudaFuncAttributeMaxDynamicSharedMemorySize, PQ_TOTAL);
    cudaFuncSetAttribute((const void*)edge_mma,
                         cudaFuncAttributeMaxDynamicSharedMemorySize, E_TOTAL);
    cudaFuncSetAttribute((const void*)node_mma,
                         cudaFuncAttributeMaxDynamicSharedMemorySize, N_TOTAL);

    prep_all<<<7786, NTP>>>(W1m, W2m, W1u, W2u, agg);
    pq_kernel<<<(N + 127) / 128, 256, PQ_TOTAL>>>(x, b1m, P, Q, N);
    edge_mma<<<(E + 127) / 128, 256, E_TOTAL>>>(eidx, P, Q, b2m, agg, E);
    node_mma<<<(N + N_ROWS - 1) / N_ROWS, 256, N_TOTAL>>>(x, agg, b1u, b2u, out, N);
}

// round 16
// speedup vs baseline: 1.8229x; 1.0489x over previous
#include <cuda_runtime.h>
#include <cuda_fp16.h>
#include <cstdint>

#define NTP 256

__device__ float g_agg[50000 * 128];
__device__ __align__(16) __half g_P[50000 * 512];   // x@W1m_top + b1m  (fp16)
__device__ __align__(16) __half g_Q[50000 * 512];   // x@W1m_bot        (fp16)
// weight images
__device__ __align__(16) __half g_w1pre[16 * 64 * 136]; // [16 nchunk64][64n][136k(128 used)]
__device__ __align__(16) __half g_w2m[8 * 128 * 72];    // [8 kchunk64][128n][72k]
__device__ __align__(16) __half g_w1u[8 * 64 * 264];    // [8 nchunk64][64n][264k(256 used)]
__device__ __align__(16) __half g_w2u[8 * 128 * 72];

__device__ __forceinline__ uint32_t smem_u32(const void* p) {
    uint32_t a;
    asm("{ .reg .u64 t; cvta.to.shared.u64 t, %1; cvt.u32.u64 %0, t; }" : "=r"(a) : "l"(p));
    return a;
}
__device__ __forceinline__ void ldm4(uint32_t addr, uint32_t* r) {
    asm volatile("ldmatrix.sync.aligned.m8n8.x4.shared.b16 {%0,%1,%2,%3}, [%4];"
                 : "=r"(r[0]), "=r"(r[1]), "=r"(r[2]), "=r"(r[3]) : "r"(addr));
}
__device__ __forceinline__ void mma_f16(float* c, const uint32_t* a,
                                        uint32_t b0, uint32_t b1) {
    asm volatile(
        "mma.sync.aligned.m16n8k16.row.col.f32.f16.f16.f32 "
        "{%0,%1,%2,%3}, {%4,%5,%6,%7}, {%8,%9}, {%0,%1,%2,%3};"
        : "+f"(c[0]), "+f"(c[1]), "+f"(c[2]), "+f"(c[3])
        : "r"(a[0]), "r"(a[1]), "r"(a[2]), "r"(a[3]), "r"(b0), "r"(b1));
}
__device__ __forceinline__ void cp16(uint32_t dst, const void* src) {
    asm volatile("cp.async.cg.shared.global [%0], [%1], 16;" :: "r"(dst), "l"(src));
}
__device__ __forceinline__ uint32_t h2bits(__half2 v) {
    return *reinterpret_cast<uint32_t*>(&v);
}
__device__ __forceinline__ void red_v4(float* p, float a, float b, float c, float d) {
    asm volatile("red.global.add.v4.f32 [%0], {%1,%2,%3,%4};"
                 :: "l"(p), "f"(a), "f"(b), "f"(c), "f"(d) : "memory");
}

// ---- merged prep: zero agg + weight images ----
// blocks: agg [0,6250) | w1pre [6250,6762) | w2m [6762,7018) | w1u [7018,7530) | w2u [7530,7786)
__global__ void prep_all(const float* __restrict__ W1m, const float* __restrict__ W2m,
                         const float* __restrict__ W1u, const float* __restrict__ W2u,
                         float* __restrict__ agg) {
    int b = blockIdx.x, tid = threadIdx.x;
    if (b < 6250) {
        ((float4*)agg)[b * NTP + tid] = make_float4(0.f, 0.f, 0.f, 0.f);
    } else if (b < 6762) {          // w1pre: W1m[256k x 512n] -> ncat = n + 512*(k>=128)
        int idx = (b - 6250) * NTP + tid;
        int k = idx >> 9, n = idx & 511;
        int ncat = (k < 128) ? n : n + 512;
        int kk = k & 127;
        g_w1pre[(ncat >> 6) * 8704 + (ncat & 63) * 136 + kk] = __float2half_rn(W1m[idx]);
    } else if (b < 7018) {          // w2m: [8 c(k64)][128n][72k]
        int idx = (b - 6762) * NTP + tid;
        int k = idx >> 7, n = idx & 127;
        g_w2m[(k >> 6) * 9216 + n * 72 + (k & 63)] = __float2half_rn(W2m[idx]);
    } else if (b < 7530) {          // w1u: [8 c(n64)][64n][264k]
        int idx = (b - 7018) * NTP + tid;
        int k = idx >> 9, n = idx & 511;
        g_w1u[(n >> 6) * 16896 + (n & 63) * 264 + k] = __float2half_rn(W1u[idx]);
    } else {                        // w2u
        int idx = (b - 7530) * NTP + tid;
        int k = idx >> 7, n = idx & 127;
        g_w2u[(k >> 6) * 9216 + n * 72 + (k & 63)] = __float2half_rn(W2u[idx]);
    }
}

// ---- precompute P = x@W1top + b1, Q = x@W1bot (fp16 out) ----
#define PQ_SMA 0          // 128 x 136 halfs (stride 272B) = 34816
#define PQ_SMW 34816      // 2 bufs x 17408
#define PQ_TOTAL 69632
__global__ __launch_bounds__(256, 1)
void pq_kernel(const float* __restrict__ x, const float* __restrict__ b1,
               __half* __restrict__ P, __half* __restrict__ Q, int N) {
    extern __shared__ __align__(16) unsigned char smem[];
    const uint32_t sb = smem_u32(smem);
    const int tid = threadIdx.x;
    const int lane = tid & 31;
    const int wid = tid >> 5;
    const int wm = wid & 3, wn = wid >> 2;
    const int rowb = blockIdx.x * 128;

#pragma unroll
    for (int cb = 0; cb < 2; ++cb) {
        const char* s = ((const char*)g_w1pre) + cb * 17408;
#pragma unroll
        for (int j = 0; j < 5; ++j) {
            int idx = tid + j * 256;
            if (idx < 1088) cp16(sb + PQ_SMW + cb * 17408 + idx * 16, s + idx * 16);
        }
        asm volatile("cp.async.commit_group;");
    }

    {
        int r = tid >> 1, half = tid & 1;
        int g = rowb + r;
        const float* src = x + (size_t)((g < N) ? g : 0) * 128 + half * 64;
        uint32_t abase = sb + PQ_SMA + (uint32_t)(r * 272 + half * 128);
#pragma unroll
        for (int jj = 0; jj < 16; ++jj) {
            float4 v = *(const float4*)(src + jj * 4);
            uint32_t h0 = h2bits(__float22half2_rn(make_float2(v.x, v.y)));
            uint32_t h1 = h2bits(__float22half2_rn(make_float2(v.z, v.w)));
            asm volatile("st.shared.v2.b32 [%0], {%1,%2};"
                         :: "r"(abase + jj * 8), "r"(h0), "r"(h1) : "memory");
        }
    }

    uint32_t aB[2];
#pragma unroll
    for (int mf = 0; mf < 2; ++mf)
        aB[mf] = sb + PQ_SMA +
            (uint32_t)((wm * 32 + mf * 16 + (lane & 15)) * 272 + ((lane >> 4) & 1) * 16);
    const uint32_t bOff = (uint32_t)((wn * 32 + (lane & 7) + ((lane >> 4) & 1) * 8) * 272 +
                                     ((lane >> 3) & 1) * 16);
    const int rsub = lane >> 2;
    const int cc = (lane & 3) * 2;

    for (int c = 0; c < 16; ++c) {
        if (c == 15) asm volatile("cp.async.wait_group 0;");
        else         asm volatile("cp.async.wait_group 1;");
        __syncthreads();
        const uint32_t wb = sb + PQ_SMW + (uint32_t)(c & 1) * 17408;

        float acc[32];
#pragma unroll
        for (int i = 0; i < 32; ++i) acc[i] = 0.f;
#pragma unroll
        for (int s = 0; s < 8; ++s) {
            uint32_t a0[4], a1[4], b0[4], b1r[4];
            ldm4(aB[0] + s * 32, a0);
            ldm4(aB[1] + s * 32, a1);
            ldm4(wb + bOff + s * 32, b0);
            ldm4(wb + bOff + 16 * 272 + s * 32, b1r);
            mma_f16(acc + 0,  a0, b0[0], b0[1]);
            mma_f16(acc + 4,  a0, b0[2], b0[3]);
            mma_f16(acc + 8,  a0, b1r[0], b1r[1]);
            mma_f16(acc + 12, a0, b1r[2], b1r[3]);
            mma_f16(acc + 16, a1, b0[0], b0[1]);
            mma_f16(acc + 20, a1, b0[2], b0[3]);
            mma_f16(acc + 24, a1, b1r[0], b1r[1]);
            mma_f16(acc + 28, a1, b1r[2], b1r[3]);
        }
        __syncthreads();
        if (c + 2 < 16) {
            const char* s = ((const char*)g_w1pre) + (c + 2) * 17408;
            uint32_t d = sb + PQ_SMW + (uint32_t)(c & 1) * 17408;
#pragma unroll
            for (int j = 0; j < 5; ++j) {
                int idx = tid + j * 256;
                if (idx < 1088) cp16(d + idx * 16, s + idx * 16);
            }
        }
        asm volatile("cp.async.commit_group;");

        bool isP = (c < 8);
        __half* dst = isP ? P : Q;
        int colbase = (isP ? c : c - 8) * 64;
#pragma unroll
        for (int mf = 0; mf < 2; ++mf) {
            int r0 = rowb + wm * 32 + mf * 16 + rsub;
#pragma unroll
            for (int ng = 0; ng < 4; ++ng) {
                const float* ac = acc + mf * 16 + ng * 4;
                int col = wn * 32 + ng * 8 + cc;
                float ba = 0.f, bb = 0.f;
                if (isP) { ba = __ldg(b1 + colbase + col); bb = __ldg(b1 + colbase + col + 1); }
                uint32_t v0 = h2bits(__float22half2_rn(make_float2(ac[0] + ba, ac[1] + bb)));
                uint32_t v1 = h2bits(__float22half2_rn(make_float2(ac[2] + ba, ac[3] + bb)));
                if (r0 < N)
                    *(uint32_t*)(dst + (size_t)r0 * 512 + colbase + col) = v0;
                if (r0 + 8 < N)
                    *(uint32_t*)(dst + (size_t)(r0 + 8) * 512 + colbase + col) = v1;
            }
        }
    }
}

// ---- edge kernel: H = relu(P[i] + Q[j]) ; out[tgt] += H @ W2m + b2 ----
// H double-buffered (1 barrier/chunk), gather-ahead-by-1, v4 scatter.
#define E_SMH   0          // 2 bufs x (128 x 72 halfs, stride 144B) = 2 x 18432
#define E_HBUF  18432
#define E_SMW2  36864      // 3 bufs x 18432
#define E_SMI   92160      // 128 int i + 128 int j
#define E_TOTAL 93184
__global__ __launch_bounds__(256, 2)
void edge_mma(const int* __restrict__ eidx,
              const __half* __restrict__ P, const __half* __restrict__ Q,
              const float* __restrict__ b2, float* __restrict__ out, int E) {
    extern __shared__ __align__(16) unsigned char smem[];
    const uint32_t sb = smem_u32(smem);
    int* sI = (int*)(smem + E_SMI);
    int* sJ = sI + 128;
    const int tid = threadIdx.x;
    const int lane = tid & 31;
    const int wid = tid >> 5;
    const int wm = wid & 3, wn = wid >> 2;
    const int rowbase = blockIdx.x * 128;

    // W2 chunks 0,1 in flight
#pragma unroll
    for (int cb = 0; cb < 2; ++cb) {
        const char* s = ((const char*)g_w2m) + cb * 18432;
#pragma unroll
        for (int j = 0; j < 5; ++j) {
            int idx = tid + j * 256;
            if (idx < 1152) cp16(sb + E_SMW2 + cb * 18432 + idx * 16, s + idx * 16);
        }
        asm volatile("cp.async.commit_group;");
    }

    if (tid < 128) {
        int row = rowbase + tid;
        int e = (row < E) ? row : 0;
        sI[tid] = eidx[E + e];   // target i
        sJ[tid] = eidx[e];       // source j
    }
    __syncthreads();

    const uint32_t hB0 = sb + E_SMH +
        (uint32_t)((wm * 32 + (lane & 15)) * 144 + ((lane >> 4) & 1) * 16);
    const uint32_t hB1 = hB0 + 16 * 144;
    uint32_t w2Off[4];
#pragma unroll
    for (int p = 0; p < 4; ++p)
        w2Off[p] = (uint32_t)((wn * 64 + p * 16 + (lane & 7) + ((lane >> 4) & 1) * 8) * 144 +
                              ((lane >> 3) & 1) * 16);

    float acc2[64];
#pragma unroll
    for (int i = 0; i < 64; ++i) acc2[i] = 0.f;

    const int gr = tid >> 1;         // gather row 0..127
    const int gh = tid & 1;          // col half (32 cols)
    const size_t pRow = (size_t)sI[gr] * 512;
    const size_t qRow = (size_t)sJ[gr] * 512;
    const uint32_t hSt = sb + E_SMH + (uint32_t)(gr * 144 + gh * 64);
    const __half2 z2 = __float2half2_rn(0.f);

    uint4 pv[4], qv[4];
    // gather chunk 0 and fill H buf 0 (visible at first loop barrier)
    {
        const uint4* pp = (const uint4*)(P + pRow + gh * 32);
        const uint4* qq = (const uint4*)(Q + qRow + gh * 32);
#pragma unroll
        for (int j = 0; j < 4; ++j) { pv[j] = __ldg(pp + j); qv[j] = __ldg(qq + j); }
#pragma unroll
        for (int j = 0; j < 4; ++j) {
            __half2* ph = (__half2*)&pv[j];
            __half2* qh = (__half2*)&qv[j];
            uint32_t o[4];
#pragma unroll
            for (int q = 0; q < 4; ++q)
                o[q] = h2bits(__hmax2(__hadd2(ph[q], qh[q]), z2));
            asm volatile("st.shared.v4.b32 [%0], {%1,%2,%3,%4};"
                         :: "r"(hSt + j * 16), "r"(o[0]), "r"(o[1]), "r"(o[2]), "r"(o[3])
                         : "memory");
        }
        // gather chunk 1
        const uint4* pp1 = (const uint4*)(P + pRow + 64 + gh * 32);
        const uint4* qq1 = (const uint4*)(Q + qRow + 64 + gh * 32);
#pragma unroll
        for (int j = 0; j < 4; ++j) { pv[j] = __ldg(pp1 + j); qv[j] = __ldg(qq1 + j); }
    }

    for (int c = 0; c < 8; ++c) {
        if (c == 7) asm volatile("cp.async.wait_group 0;");
        else        asm volatile("cp.async.wait_group 1;");
        __syncthreads();   // H(c) visible; W2 buf (c+2)%3 free; W2(c) resident

        if (c + 2 < 8) {
            const char* s = ((const char*)g_w2m) + (c + 2) * 18432;
            uint32_t d = sb + E_SMW2 + (uint32_t)((c + 2) % 3) * 18432;
#pragma unroll
            for (int j = 0; j < 5; ++j) {
                int idx = tid + j * 256;
                if (idx < 1152) cp16(d + idx * 16, s + idx * 16);
            }
            asm volatile("cp.async.commit_group;");
        }

        // relu(c+1) from pre-gathered registers -> H buf (c+1)&1
        if (c + 1 < 8) {
            uint32_t hs = hSt + (uint32_t)((c + 1) & 1) * E_HBUF;
#pragma unroll
            for (int j = 0; j < 4; ++j) {
                __half2* ph = (__half2*)&pv[j];
                __half2* qh = (__half2*)&qv[j];
                uint32_t o[4];
#pragma unroll
                for (int q = 0; q < 4; ++q)
                    o[q] = h2bits(__hmax2(__hadd2(ph[q], qh[q]), z2));
                asm volatile("st.shared.v4.b32 [%0], {%1,%2,%3,%4};"
                             :: "r"(hs + j * 16), "r"(o[0]), "r"(o[1]), "r"(o[2]), "r"(o[3])
                             : "memory");
            }
        }
        // issue gather(c+2) — a full GEMM2 of latency cover
        if (c + 2 < 8) {
            const uint4* pp = (const uint4*)(P + pRow + (c + 2) * 64 + gh * 32);
            const uint4* qq = (const uint4*)(Q + qRow + (c + 2) * 64 + gh * 32);
#pragma unroll
            for (int j = 0; j < 4; ++j) { pv[j] = __ldg(pp + j); qv[j] = __ldg(qq + j); }
        }

        // GEMM2: acc2 += H[128x64] @ W2chunk[64x128]
        const uint32_t w2b = sb + E_SMW2 + (uint32_t)(c % 3) * 18432;
        const uint32_t hb = (uint32_t)(c & 1) * E_HBUF;
#pragma unroll
        for (int s = 0; s < 4; ++s) {
            uint32_t h0[4], h1[4];
            ldm4(hB0 + hb + s * 32, h0);
            ldm4(hB1 + hb + s * 32, h1);
#pragma unroll
            for (int p = 0; p < 4; ++p) {
                uint32_t bw[4];
                ldm4(w2b + w2Off[p] + s * 32, bw);
                mma_f16(acc2 + p * 8 + 0,      h0, bw[0], bw[1]);
                mma_f16(acc2 + p * 8 + 4,      h0, bw[2], bw[3]);
                mma_f16(acc2 + 32 + p * 8 + 0, h1, bw[0], bw[1]);
                mma_f16(acc2 + 32 + p * 8 + 4, h1, bw[2], bw[3]);
            }
        }
    }

    // scatter: out[tgt] += acc2 + b2 — v4 via lane-pair shuffle
#pragma unroll
    for (int mf = 0; mf < 2; ++mf) {
        int r_lo = wm * 32 + mf * 16 + (lane >> 2);
        int e0 = rowbase + r_lo;
        int e1 = e0 + 8;
        int tgt0 = sI[r_lo];
        int tgt1 = sI[r_lo + 8];
#pragma unroll
        for (int p = 0; p < 4; ++p) {
#pragma unroll
            for (int t = 0; t < 2; ++t) {
                const float* ac = acc2 + mf * 32 + p * 8 + t * 4;
                int colq = wn * 64 + p * 16 + t * 8 + (lane & 2) * 2;
                float sx = (lane & 1) ? ac[0] : ac[2];
                float sy = (lane & 1) ? ac[1] : ac[3];
                float rx = __shfl_xor_sync(0xffffffff, sx, 1);
                float ry = __shfl_xor_sync(0xffffffff, sy, 1);
                float4 bq = __ldg((const float4*)(b2 + colq));
                if (!(lane & 1)) {
                    if (e0 < E)
                        red_v4(out + (size_t)tgt0 * 128 + colq,
                               ac[0] + bq.x, ac[1] + bq.y, rx + bq.z, ry + bq.w);
                } else {
                    if (e1 < E)
                        red_v4(out + (size_t)tgt1 * 128 + colq,
                               rx + bq.x, ry + bq.y, ac[2] + bq.z, ac[3] + bq.w);
                }
            }
        }
    }
}

// ---- node kernel: R11 champion path (u = [x|agg] @ MLPu) ----
#define N_ROWS 192
#define N_SMA    0
#define N_SMW1   101376
#define N_SMW2   135168
#define N_SMH    153600
#define N_TOTAL  181248
__global__ __launch_bounds__(256, 1)
void node_mma(const float* __restrict__ x, const float* __restrict__ agg,
              const float* __restrict__ b1, const float* __restrict__ b2,
              float* __restrict__ out, int M) {
    extern __shared__ __align__(16) unsigned char smem[];
    const uint32_t sb = smem_u32(smem);
    const int tid = threadIdx.x;
    const int lane = tid & 31;
    const int wid = tid >> 5;
    const int wm = wid & 3, wn = wid >> 2;
    const int rowbase = blockIdx.x * N_ROWS;

    {
        const char* s = (const char*)g_w1u;
#pragma unroll
        for (int j = 0; j < 9; ++j) {
            int idx = tid + j * 256;
            if (idx < 2112) cp16(sb + N_SMW1 + idx * 16, s + idx * 16);
        }
        asm volatile("cp.async.commit_group;");
        const char* s2 = (const char*)g_w2u;
#pragma unroll
        for (int j = 0; j < 5; ++j) {
            int idx = tid + j * 256;
            if (idx < 1152) cp16(sb + N_SMW2 + idx * 16, s2 + idx * 16);
        }
        asm volatile("cp.async.commit_group;");
    }

    for (int idx = tid; idx < N_ROWS * 2; idx += 256) {
        int r = idx >> 1, half = idx & 1;
        int row = rowbase + r;
        int rr = (row < M) ? row : 0;
        const float* src = (half ? agg : x) + (size_t)rr * 128;
        uint32_t abase = sb + N_SMA + (uint32_t)(r * 528 + half * 256);
#pragma unroll
        for (int jj = 0; jj < 32; ++jj) {
            float4 v = *(const float4*)(src + jj * 4);
            uint32_t h0 = h2bits(__float22half2_rn(make_float2(v.x, v.y)));
            uint32_t h1 = h2bits(__float22half2_rn(make_float2(v.z, v.w)));
            asm volatile("st.shared.v2.b32 [%0], {%1,%2};"
                         :: "r"(abase + jj * 8), "r"(h0), "r"(h1) : "memory");
        }
    }

    uint32_t aB[3], hB[3];
#pragma unroll
    for (int mf = 0; mf < 3; ++mf) {
        aB[mf] = sb + N_SMA +
            (uint32_t)((wm * 48 + mf * 16 + (lane & 15)) * 528 + ((lane >> 4) & 1) * 16);
        hB[mf] = sb + N_SMH +
            (uint32_t)((wm * 48 + mf * 16 + (lane & 15)) * 144 + ((lane >> 4) & 1) * 16);
    }
    const uint32_t bB0 = sb + N_SMW1 +
        (uint32_t)((wn * 32 + (lane & 7) + ((lane >> 4) & 1) * 8) * 528 +
                   ((lane >> 3) & 1) * 16);
    const uint32_t bB1 = bB0 + 16 * 528;
    uint32_t w2B[4];
#pragma unroll
    for (int p = 0; p < 4; ++p)
        w2B[p] = sb + N_SMW2 +
            (uint32_t)((wn * 64 + p * 16 + (lane & 7) + ((lane >> 4) & 1) * 8) * 144 +
                       ((lane >> 3) & 1) * 16);

    float acc2[96];
#pragma unroll
    for (int i = 0; i < 96; ++i) acc2[i] = 0.f;
    const int rsub = lane >> 2;
    const int cc = (lane & 3) * 2;

    for (int c = 0; c < 8; ++c) {
        asm volatile("cp.async.wait_group 1;");
        __syncthreads();
        float acc1[48];
#pragma unroll
        for (int i = 0; i < 48; ++i) acc1[i] = 0.f;
#pragma unroll
        for (int s = 0; s < 16; ++s) {
            uint32_t a0[4], a1[4], a2[4], b0[4], b1r[4];
            ldm4(aB[0] + s * 32, a0);
            ldm4(aB[1] + s * 32, a1);
            ldm4(aB[2] + s * 32, a2);
            ldm4(bB0 + s * 32, b0);
            ldm4(bB1 + s * 32, b1r);
            mma_f16(acc1 + 0,  a0, b0[0], b0[1]);
            mma_f16(acc1 + 4,  a0, b0[2], b0[3]);
            mma_f16(acc1 + 8,  a0, b1r[0], b1r[1]);
            mma_f16(acc1 + 12, a0, b1r[2], b1r[3]);
            mma_f16(acc1 + 16, a1, b0[0], b0[1]);
            mma_f16(acc1 + 20, a1, b0[2], b0[3]);
            mma_f16(acc1 + 24, a1, b1r[0], b1r[1]);
            mma_f16(acc1 + 28, a1, b1r[2], b1r[3]);
            mma_f16(acc1 + 32, a2, b0[0], b0[1]);
            mma_f16(acc1 + 36, a2, b0[2], b0[3]);
            mma_f16(acc1 + 40, a2, b1r[0], b1r[1]);
            mma_f16(acc1 + 44, a2, b1r[2], b1r[3]);
        }
#pragma unroll
        for (int mf = 0; mf < 3; ++mf) {
#pragma unroll
            for (int nq = 0; nq < 4; ++nq) {
                const float* ac = acc1 + mf * 16 + nq * 4;
                int gcol = c * 64 + wn * 32 + nq * 8 + cc;
                float ba = __ldg(b1 + gcol), bb = __ldg(b1 + gcol + 1);
                float v00 = fmaxf(ac[0] + ba, 0.f);
                float v01 = fmaxf(ac[1] + bb, 0.f);
                float v10 = fmaxf(ac[2] + ba, 0.f);
                float v11 = fmaxf(ac[3] + bb, 0.f);
                uint32_t p0 = h2bits(__float22half2_rn(make_float2(v00, v01)));
                uint32_t p1 = h2bits(__float22half2_rn(make_float2(v10, v11)));
                int hcol = wn * 32 + nq * 8 + cc;
                int r0 = wm * 48 + mf * 16 + rsub;
                uint32_t a0 = sb + N_SMH + (uint32_t)(r0 * 144 + hcol * 2);
                asm volatile("st.shared.b32 [%0], %1;" :: "r"(a0), "r"(p0) : "memory");
                asm volatile("st.shared.b32 [%0], %1;" :: "r"(a0 + 8 * 144), "r"(p1) : "memory");
            }
        }
        __syncthreads();
        if (c + 1 < 8) {
            const char* s = ((const char*)g_w1u) + (c + 1) * 33792;
#pragma unroll
            for (int j = 0; j < 9; ++j) {
                int idx = tid + j * 256;
                if (idx < 2112) cp16(sb + N_SMW1 + idx * 16, s + idx * 16);
            }
            asm volatile("cp.async.commit_group;");
            asm volatile("cp.async.wait_group 1;");
        } else {
            asm volatile("cp.async.wait_group 0;");
        }
        __syncthreads();
#pragma unroll
        for (int s = 0; s < 4; ++s) {
            uint32_t h0[4], h1[4], h2[4];
            ldm4(hB[0] + s * 32, h0);
            ldm4(hB[1] + s * 32, h1);
            ldm4(hB[2] + s * 32, h2);
#pragma unroll
            for (int p = 0; p < 4; ++p) {
                uint32_t bw[4];
                ldm4(w2B[p] + s * 32, bw);
                mma_f16(acc2 + p * 8 + 0,  h0, bw[0], bw[1]);
                mma_f16(acc2 + p * 8 + 4,  h0, bw[2], bw[3]);
                mma_f16(acc2 + 32 + p * 8 + 0, h1, bw[0], bw[1]);
                mma_f16(acc2 + 32 + p * 8 + 4, h1, bw[2], bw[3]);
                mma_f16(acc2 + 64 + p * 8 + 0, h2, bw[0], bw[1]);
                mma_f16(acc2 + 64 + p * 8 + 4, h2, bw[2], bw[3]);
            }
        }
        __syncthreads();
        if (c + 1 < 8) {
            const char* s = ((const char*)g_w2u) + (c + 1) * 18432;
#pragma unroll
            for (int j = 0; j < 5; ++j) {
                int idx = tid + j * 256;
                if (idx < 1152) cp16(sb + N_SMW2 + idx * 16, s + idx * 16);
            }
        }
        asm volatile("cp.async.commit_group;");
    }

#pragma unroll
    for (int mf = 0; mf < 3; ++mf) {
        int e0 = rowbase + wm * 48 + mf * 16 + rsub;
        int e1 = e0 + 8;
#pragma unroll
        for (int p = 0; p < 4; ++p) {
#pragma unroll
            for (int t = 0; t < 2; ++t) {
                const float* ac = acc2 + mf * 32 + p * 8 + t * 4;
                int col = wn * 64 + p * 16 + t * 8 + cc;
                float ba = __ldg(b2 + col), bb = __ldg(b2 + col + 1);
                if (e0 < M) *(float2*)(out + (size_t)e0 * 128 + col) = make_float2(ac[0] + ba, ac[1] + bb);
                if (e1 < M) *(float2*)(out + (size_t)e1 * 128 + col) = make_float2(ac[2] + ba, ac[3] + bb);
            }
        }
    }
}

extern "C" void kernel_launch(void* const* d_in, const int* in_sizes, int n_in,
                              void* d_out, int out_size) {
    const float* x   = (const float*)d_in[0];
    const int* eidx  = (const int*)d_in[2];   // JAX demotes int64 -> int32
    const float* W1m = (const float*)d_in[3];
    const float* b1m = (const float*)d_in[4];
    const float* W2m = (const float*)d_in[5];
    const float* b2m = (const float*)d_in[6];
    const float* W1u = (const float*)d_in[7];
    const float* b1u = (const float*)d_in[8];
    const float* W2u = (const float*)d_in[9];
    const float* b2u = (const float*)d_in[10];
    float* out = (float*)d_out;

    int N = in_sizes[0] / 128;
    int E = in_sizes[2] / 2;

    float* agg; cudaGetSymbolAddress((void**)&agg, g_agg);
    __half *P, *Q;
    cudaGetSymbolAddress((void**)&P, g_P);
    cudaGetSymbolAddress((void**)&Q, g_Q);

    cudaFuncSetAttribute((const void*)pq_kernel,
                         cudaFuncAttributeMaxDynamicSharedMemorySize, PQ_TOTAL);
    cudaFuncSetAttribute((const void*)edge_mma,
                         cudaFuncAttributeMaxDynamicSharedMemorySize, E_TOTAL);
    cudaFuncSetAttribute((const void*)node_mma,
                         cudaFuncAttributeMaxDynamicSharedMemorySize, N_TOTAL);

    prep_all<<<7786, NTP>>>(W1m, W2m, W1u, W2u, agg);
    pq_kernel<<<(N + 127) / 128, 256, PQ_TOTAL>>>(x, b1m, P, Q, N);
    edge_mma<<<(E + 127) / 128, 256, E_TOTAL>>>(eidx, P, Q, b2m, agg, E);
    node_mma<<<(N + N_ROWS - 1) / N_ROWS, 256, N_TOTAL>>>(x, agg, b1u, b2u, out, N);
}